// round 1
// baseline (speedup 1.0000x reference)
#include <cuda_runtime.h>
#include <math.h>

#define N_USER 60000
#define N_ITEM 40000
#define NN     100000
#define D      64
#define NNZ    1600000
#define BB     16384
#define NLAYERS 2

// ---------------- scratch (device globals; no allocation allowed) ----------------
__device__ float g_X[NN * D];         // current layer features
__device__ float g_S[NN * D];         // spmm(X)
__device__ float g_S2[NN * D];        // spmm(X*X)
__device__ float g_h12[3][NN * D];    // per-relation h1+h2
__device__ float g_facc[NN * D];      // running sum of all_emb
__device__ int   g_rowptr[3][NN + 1];
__device__ int   g_colS[3][NNZ];
__device__ float g_valS[3][NNZ];
__device__ int   g_count[NN];
__device__ int   g_cursor[NN];
__device__ float g_attsum[3];         // indexed by relation: 0=lap(main),1=trust,2=add
__device__ float g_betaRel[3];        // beta indexed by relation

// ---------------- kernels ----------------

__global__ void zero_att_kernel() {
    if (threadIdx.x < 3) g_attsum[threadIdx.x] = 0.f;
}

__global__ void init_feats_kernel(const float* __restrict__ uE, const float* __restrict__ iE) {
    int i = blockIdx.x * blockDim.x + threadIdx.x;
    if (i < NN * D) {
        float v = (i < N_USER * D) ? uE[i] : iE[i - N_USER * D];
        g_X[i] = v;
        g_facc[i] = v;
    }
}

__global__ void zero_count_kernel() {
    int i = blockIdx.x * blockDim.x + threadIdx.x;
    if (i < NN) g_count[i] = 0;
}

__global__ void hist_kernel(const int* __restrict__ row) {
    int e = blockIdx.x * blockDim.x + threadIdx.x;
    if (e < NNZ) atomicAdd(&g_count[row[e]], 1);
}

// single-block exclusive scan over g_count -> g_rowptr[r], g_cursor
__global__ void scan_kernel(int r) {
    __shared__ int s[1024];
    __shared__ int run;
    int tid = threadIdx.x;
    if (tid == 0) run = 0;
    __syncthreads();
    for (int base = 0; base < NN; base += 1024) {
        int c = (base + tid < NN) ? g_count[base + tid] : 0;
        s[tid] = c;
        __syncthreads();
        for (int off = 1; off < 1024; off <<= 1) {
            int t = (tid >= off) ? s[tid - off] : 0;
            __syncthreads();
            s[tid] += t;
            __syncthreads();
        }
        int excl = run + s[tid] - c;
        if (base + tid < NN) {
            g_rowptr[r][base + tid] = excl;
            g_cursor[base + tid] = excl;
        }
        __syncthreads();
        if (tid == 0) run += s[1023];
        __syncthreads();
    }
    if (tid == 0) g_rowptr[r][NN] = run;
}

__global__ void scatter_kernel(int r, const int* __restrict__ row,
                               const int* __restrict__ col, const float* __restrict__ val) {
    int e = blockIdx.x * blockDim.x + threadIdx.x;
    if (e < NNZ) {
        int rr = row[e];
        int pos = atomicAdd(&g_cursor[rr], 1);
        g_colS[r][pos] = col[e];
        g_valS[r][pos] = val[e];
    }
}

// fused spmm: S = A@X, S2 = A@(X*X). one warp per row, float2 per lane.
__global__ void spmm_kernel(int r) {
    int gw = (blockIdx.x * blockDim.x + threadIdx.x) >> 5;
    int lane = threadIdx.x & 31;
    if (gw >= NN) return;
    const int* __restrict__ cs = g_colS[r];
    const float* __restrict__ vs = g_valS[r];
    int beg = g_rowptr[r][gw], end = g_rowptr[r][gw + 1];
    float a0 = 0.f, a1 = 0.f, b0 = 0.f, b1 = 0.f;
    int e = beg;
    for (; e + 1 < end; e += 2) {            // pairwise to double MLP
        int   c0 = cs[e],     c1 = cs[e + 1];
        float v0 = vs[e],     v1 = vs[e + 1];
        float2 x0 = *(const float2*)&g_X[c0 * D + 2 * lane];
        float2 x1 = *(const float2*)&g_X[c1 * D + 2 * lane];
        a0 += v0 * x0.x + v1 * x1.x;
        a1 += v0 * x0.y + v1 * x1.y;
        b0 += v0 * x0.x * x0.x + v1 * x1.x * x1.x;
        b1 += v0 * x0.y * x0.y + v1 * x1.y * x1.y;
    }
    if (e < end) {
        int c0 = cs[e]; float v0 = vs[e];
        float2 x0 = *(const float2*)&g_X[c0 * D + 2 * lane];
        a0 += v0 * x0.x; a1 += v0 * x0.y;
        b0 += v0 * x0.x * x0.x; b1 += v0 * x0.y * x0.y;
    }
    *(float2*)&g_S [gw * D + 2 * lane] = make_float2(a0, a1);
    *(float2*)&g_S2[gw * D + 2 * lane] = make_float2(b0, b1);
}

// fused: h12 = (S+X)@linW + S2@interW + (lin_b+inter_b); att partial = mean_n tanh(h12@aW+ab)@avec
__global__ void __launch_bounds__(256) gemm_h12_kernel(
    int r,
    const float* __restrict__ linW, const float* __restrict__ linb,
    const float* __restrict__ intW, const float* __restrict__ intb,
    const float* __restrict__ attW, const float* __restrict__ attb,
    const float* __restrict__ avec)
{
    __shared__ float wL[D * D], wI[D * D], wA[D * D];
    __shared__ float b12[D], bA[D], aV[D];
    __shared__ float rowS[8][D], rowS2[8][D], rowH[8][D];

    int tid = threadIdx.x;
    for (int i = tid; i < D * D; i += 256) {
        wL[i] = linW[i]; wI[i] = intW[i]; wA[i] = attW[i];
    }
    if (tid < D) {
        b12[tid] = linb[tid] + intb[tid];
        bA[tid] = attb[tid];
        aV[tid] = avec[tid];
    }
    __syncthreads();

    int w = tid >> 5, lane = tid & 31;
    int warpGlobal = blockIdx.x * 8 + w;
    int nWarps = gridDim.x * 8;
    float* __restrict__ h12out = g_h12[r];
    float attAcc = 0.f;

    for (int n = warpGlobal; n < NN; n += nWarps) {
        float2 s  = *(const float2*)&g_S [n * D + 2 * lane];
        float2 x  = *(const float2*)&g_X [n * D + 2 * lane];
        float2 s2 = *(const float2*)&g_S2[n * D + 2 * lane];
        rowS [w][2 * lane]     = s.x + x.x;
        rowS [w][2 * lane + 1] = s.y + x.y;
        rowS2[w][2 * lane]     = s2.x;
        rowS2[w][2 * lane + 1] = s2.y;
        __syncwarp();

        float acc0 = b12[lane], acc1 = b12[lane + 32];
        #pragma unroll 8
        for (int d = 0; d < D; d++) {
            float sd = rowS[w][d], s2d = rowS2[w][d];
            acc0 += sd * wL[d * D + lane]      + s2d * wI[d * D + lane];
            acc1 += sd * wL[d * D + lane + 32] + s2d * wI[d * D + lane + 32];
        }
        rowH[w][lane] = acc0;
        rowH[w][lane + 32] = acc1;
        h12out[n * D + lane] = acc0;
        h12out[n * D + lane + 32] = acc1;
        __syncwarp();

        float z0 = bA[lane], z1 = bA[lane + 32];
        #pragma unroll 8
        for (int d = 0; d < D; d++) {
            float h = rowH[w][d];
            z0 += h * wA[d * D + lane];
            z1 += h * wA[d * D + lane + 32];
        }
        attAcc += tanhf(z0) * aV[lane] + tanhf(z1) * aV[lane + 32];
        __syncwarp();
    }
    #pragma unroll
    for (int off = 16; off; off >>= 1)
        attAcc += __shfl_down_sync(0xffffffffu, attAcc, off);
    if (lane == 0) atomicAdd(&g_attsum[r], attAcc);
}

__global__ void beta_kernel() {
    // attsum: [0]=main(lap), [1]=trust, [2]=add ; softmax over [main, add, trust]
    float m = g_attsum[0] / (float)NN;
    float t = g_attsum[1] / (float)NN;
    float a = g_attsum[2] / (float)NN;
    float mx = fmaxf(m, fmaxf(a, t));
    float e0 = expf(m - mx), e1 = expf(a - mx), e2 = expf(t - mx);
    float s = e0 + e1 + e2;
    g_betaRel[0] = e0 / s;   // lap  <- beta[0] (main)
    g_betaRel[1] = e2 / s;   // trust<- beta[2]
    g_betaRel[2] = e1 / s;   // add  <- beta[1]
    g_attsum[0] = 0.f; g_attsum[1] = 0.f; g_attsum[2] = 0.f;
}

__global__ void combine_kernel() {
    int i = blockIdx.x * blockDim.x + threadIdx.x;
    if (i < NN * D) {
        float v = g_betaRel[0] * g_h12[0][i]
                + g_betaRel[1] * g_h12[1][i]
                + g_betaRel[2] * g_h12[2][i];
        g_X[i] = v;
        g_facc[i] += v;
    }
}

__global__ void finalize_kernel(float* __restrict__ finalOut) {
    int i = blockIdx.x * blockDim.x + threadIdx.x;
    if (i < NN * D) finalOut[i] = g_facc[i] * (1.0f / 3.0f);
}

__global__ void mlp_kernel(const int* __restrict__ userIdx, const int* __restrict__ itemIdx,
                           const float* __restrict__ W1, const float* __restrict__ b1,
                           const float* __restrict__ W2, const float* __restrict__ b2,
                           const float* __restrict__ W3, const float* __restrict__ b3,
                           const float* __restrict__ finalE,
                           float* __restrict__ pred, float* __restrict__ outU, float* __restrict__ outI)
{
    __shared__ float h[128];
    __shared__ float h1s[64];
    __shared__ float h2s[32];
    int bI = blockIdx.x;
    int t = threadIdx.x;  // 64 threads
    int u = userIdx[bI];
    int v = itemIdx[bI] + N_USER;
    float fu = finalE[u * D + t];
    float fi = finalE[v * D + t];
    h[t] = fu; h[64 + t] = fi;
    outU[bI * D + t] = fu;
    outI[bI * D + t] = fi;
    __syncthreads();

    float acc = b1[t];
    #pragma unroll 16
    for (int k = 0; k < 128; k++) acc += h[k] * W1[k * 64 + t];
    h1s[t] = fmaxf(acc, 0.f);
    __syncthreads();

    if (t < 32) {
        float a2 = b2[t];
        #pragma unroll 16
        for (int k = 0; k < 64; k++) a2 += h1s[k] * W2[k * 32 + t];
        h2s[t] = a2;
    }
    __syncthreads();
    if (t < 32) {
        float p = h2s[t] * W3[t];
        #pragma unroll
        for (int off = 16; off; off >>= 1) p += __shfl_down_sync(0xffffffffu, p, off);
        if (t == 0) pred[bI] = p + b3[0];
    }
}

// ---------------- launch ----------------

extern "C" void kernel_launch(void* const* d_in, const int* in_sizes, int n_in,
                              void* d_out, int out_size)
{
    const int*   userIdx = (const int*)d_in[0];
    const int*   itemIdx = (const int*)d_in[1];
    const float* uEmbd   = (const float*)d_in[2];
    const float* iEmbd   = (const float*)d_in[3];

    const int*   rowP[3] = { (const int*)d_in[4],  (const int*)d_in[7],  (const int*)d_in[10] };
    const int*   colP[3] = { (const int*)d_in[5],  (const int*)d_in[8],  (const int*)d_in[11] };
    const float* valP[3] = { (const float*)d_in[6], (const float*)d_in[9], (const float*)d_in[12] };

    const float *lin_W, *lin_b, *inter_W, *inter_b;
    const float *attM_W, *attM_b, *attA_W, *attA_b, *attT_W, *attT_b;
    if (in_sizes[14] == 2 * D * D) {
        // dict order: lin_W, inter_W, attM_W, attA_W, attT_W, lin_b, inter_b, attM_b, attA_b, attT_b
        lin_W   = (const float*)d_in[13];
        inter_W = (const float*)d_in[14];
        attM_W  = (const float*)d_in[15];
        attA_W  = (const float*)d_in[16];
        attT_W  = (const float*)d_in[17];
        lin_b   = (const float*)d_in[18];
        inter_b = (const float*)d_in[19];
        attM_b  = (const float*)d_in[20];
        attA_b  = (const float*)d_in[21];
        attT_b  = (const float*)d_in[22];
    } else {
        // signature order: interleaved W,b
        lin_W   = (const float*)d_in[13];
        lin_b   = (const float*)d_in[14];
        inter_W = (const float*)d_in[15];
        inter_b = (const float*)d_in[16];
        attM_W  = (const float*)d_in[17];
        attM_b  = (const float*)d_in[18];
        attA_W  = (const float*)d_in[19];
        attA_b  = (const float*)d_in[20];
        attT_W  = (const float*)d_in[21];
        attT_b  = (const float*)d_in[22];
    }
    const float* a_main  = (const float*)d_in[23];
    const float* a_add   = (const float*)d_in[24];
    const float* a_trust = (const float*)d_in[25];
    const float* W1 = (const float*)d_in[26];
    const float* b1 = (const float*)d_in[27];
    const float* W2 = (const float*)d_in[28];
    const float* b2 = (const float*)d_in[29];
    const float* W3 = (const float*)d_in[30];
    const float* b3 = (const float*)d_in[31];

    // output layout: [pred(B)] [userE(B*D)] [itemE(B*D)] [final(N*D)]
    float* out      = (float*)d_out;
    float* predOut  = out;
    float* userOut  = out + BB;
    float* itemOut  = out + BB + BB * D;
    float* finalOut = out + BB + 2 * BB * D;

    // per-relation attention params: rel0=lap->M/main, rel1=trust->T/trust, rel2=add->A/add
    const float* attWrel[3] = { attM_W, attT_W, attA_W };
    const float* attBrel[3] = { attM_b, attT_b, attA_b };
    const float* avecRel[3] = { a_main, a_trust, a_add };

    const int TPB = 256;
    const int ND_BLOCKS = (NN * D + TPB - 1) / TPB;

    zero_att_kernel<<<1, 32>>>();
    init_feats_kernel<<<ND_BLOCKS, TPB>>>(uEmbd, iEmbd);

    // CSR build per relation
    for (int r = 0; r < 3; r++) {
        zero_count_kernel<<<(NN + TPB - 1) / TPB, TPB>>>();
        hist_kernel<<<(NNZ + TPB - 1) / TPB, TPB>>>(rowP[r]);
        scan_kernel<<<1, 1024>>>(r);
        scatter_kernel<<<(NNZ + TPB - 1) / TPB, TPB>>>(r, rowP[r], colP[r], valP[r]);
    }

    for (int l = 0; l < NLAYERS; l++) {
        for (int r = 0; r < 3; r++) {
            spmm_kernel<<<(NN * 32 + TPB - 1) / TPB, TPB>>>(r);
            gemm_h12_kernel<<<1184, 256>>>(
                r,
                lin_W   + l * D * D, lin_b   + l * D,
                inter_W + l * D * D, inter_b + l * D,
                attWrel[r] + l * D * D, attBrel[r] + l * D,
                avecRel[r] + l * D);
        }
        beta_kernel<<<1, 1>>>();
        combine_kernel<<<ND_BLOCKS, TPB>>>();
    }

    finalize_kernel<<<ND_BLOCKS, TPB>>>(finalOut);
    mlp_kernel<<<BB, 64>>>(userIdx, itemIdx, W1, b1, W2, b2, W3, b3,
                           finalOut, predOut, userOut, itemOut);
}

// round 2
// speedup vs baseline: 1.9475x; 1.9475x over previous
#include <cuda_runtime.h>
#include <math.h>

#define N_USER 60000
#define N_ITEM 40000
#define NN     100000
#define D      64
#define NNZ    1600000
#define BB     16384
#define NLAYERS 2
#define NB     98          // ceil(NN/1024)

typedef unsigned long long u64;

// ---------------- packed f32x2 helpers ----------------
__device__ __forceinline__ u64 f2dup(float v) {
    u64 r; asm("mov.b64 %0,{%1,%1};" : "=l"(r) : "f"(v)); return r;
}
__device__ __forceinline__ u64 ffma2(u64 a, u64 b, u64 c) {
    u64 d; asm("fma.rn.f32x2 %0,%1,%2,%3;" : "=l"(d) : "l"(a), "l"(b), "l"(c)); return d;
}
__device__ __forceinline__ u64 fmul2(u64 a, u64 b) {
    u64 d; asm("mul.rn.f32x2 %0,%1,%2;" : "=l"(d) : "l"(a), "l"(b)); return d;
}
__device__ __forceinline__ void funpack2(u64 v, float& lo, float& hi) {
    asm("mov.b64 {%0,%1},%2;" : "=f"(lo), "=f"(hi) : "l"(v));
}

// ---------------- scratch ----------------
__device__ float g_X[NN * D];
__device__ float g_facc[NN * D];
__device__ float g_S3[3][NN * D];
__device__ float g_S2_3[3][NN * D];
__device__ float g_h12[3][NN * D];
__device__ int   g_rowptr[3][NN + 1];
__device__ int   g_colS[3][NNZ];
__device__ float g_valS[3][NNZ];
__device__ int   g_count3[3][NN];
__device__ int   g_cursor3[3][NN];
__device__ int   g_blk[3][128];
__device__ float g_attsum[3];
__device__ float g_betaRel[3];

// ---------------- small kernels ----------------
__global__ void zero3_kernel() {
    int i = blockIdx.x * blockDim.x + threadIdx.x;
    if (i < 3 * NN) ((int*)g_count3)[i] = 0;
    if (i < 3) g_attsum[i] = 0.f;
}

__global__ void init_feats_kernel(const float* __restrict__ uE, const float* __restrict__ iE) {
    int i4 = blockIdx.x * blockDim.x + threadIdx.x;
    if (i4 < NN * D / 4) {
        int i = i4 * 4;
        float4 v = (i < N_USER * D) ? ((const float4*)uE)[i4]
                                    : ((const float4*)iE)[i4 - N_USER * D / 4];
        ((float4*)g_X)[i4] = v;
        ((float4*)g_facc)[i4] = v;
    }
}

__global__ void hist3_kernel(const int* __restrict__ r0, const int* __restrict__ r1,
                             const int* __restrict__ r2) {
    int r = blockIdx.y;
    const int* row = (r == 0) ? r0 : (r == 1) ? r1 : r2;
    int e = blockIdx.x * blockDim.x + threadIdx.x;
    if (e < NNZ) atomicAdd(&g_count3[r][row[e]], 1);
}

__global__ void scan_local_kernel() {
    __shared__ int s[1024];
    int r = blockIdx.y;
    int i = blockIdx.x * 1024 + threadIdx.x;
    int c = (i < NN) ? g_count3[r][i] : 0;
    s[threadIdx.x] = c;
    __syncthreads();
    for (int off = 1; off < 1024; off <<= 1) {
        int t = (threadIdx.x >= off) ? s[threadIdx.x - off] : 0;
        __syncthreads();
        s[threadIdx.x] += t;
        __syncthreads();
    }
    if (i < NN) g_rowptr[r][i] = s[threadIdx.x] - c;   // local exclusive
    if (threadIdx.x == 1023) g_blk[r][blockIdx.x] = s[1023];
}

__global__ void scan_blk_kernel() {
    __shared__ int s[3 * NB];
    int tid = threadIdx.x;
    for (int i = tid; i < 3 * NB; i += blockDim.x) s[i] = g_blk[i / NB][i % NB];
    __syncthreads();
    if (tid < 3) {
        int run = 0;
        for (int b = 0; b < NB; b++) { int t = s[tid * NB + b]; s[tid * NB + b] = run; run += t; }
        g_rowptr[tid][NN] = run;
    }
    __syncthreads();
    for (int i = tid; i < 3 * NB; i += blockDim.x) g_blk[i / NB][i % NB] = s[i];
}

__global__ void fixup_kernel() {
    int r = blockIdx.y;
    int i = blockIdx.x * 1024 + threadIdx.x;
    if (i < NN) {
        int v = g_rowptr[r][i] + g_blk[r][blockIdx.x];
        g_rowptr[r][i] = v;
        g_cursor3[r][i] = v;
    }
}

__global__ void scatter3_kernel(const int* __restrict__ r0, const int* __restrict__ r1,
                                const int* __restrict__ r2,
                                const int* __restrict__ c0, const int* __restrict__ c1,
                                const int* __restrict__ c2,
                                const float* __restrict__ v0, const float* __restrict__ v1,
                                const float* __restrict__ v2) {
    int r = blockIdx.y;
    const int* row = (r == 0) ? r0 : (r == 1) ? r1 : r2;
    const int* col = (r == 0) ? c0 : (r == 1) ? c1 : c2;
    const float* val = (r == 0) ? v0 : (r == 1) ? v1 : v2;
    int e = blockIdx.x * blockDim.x + threadIdx.x;
    if (e < NNZ) {
        int rr = row[e];
        int pos = atomicAdd(&g_cursor3[r][rr], 1);
        g_colS[r][pos] = col[e];
        g_valS[r][pos] = val[e];
    }
}

// fused SpMM: S = A@X, S2 = A@(X*X); warp per row, packed f32x2
__global__ void spmm3_kernel() {
    int r = blockIdx.y;
    int gw = (blockIdx.x * blockDim.x + threadIdx.x) >> 5;
    int lane = threadIdx.x & 31;
    if (gw >= NN) return;
    const int* __restrict__ cs = g_colS[r];
    const float* __restrict__ vs = g_valS[r];
    int beg = g_rowptr[r][gw], end = g_rowptr[r][gw + 1];
    u64 a = 0ull, b = 0ull;
    int e = beg;
    for (; e + 2 <= end; e += 2) {
        int   c0 = cs[e], c1 = cs[e + 1];
        float v0 = vs[e], v1 = vs[e + 1];
        u64 x0 = *(const u64*)&g_X[c0 * D + 2 * lane];
        u64 x1 = *(const u64*)&g_X[c1 * D + 2 * lane];
        u64 v0d = f2dup(v0), v1d = f2dup(v1);
        a = ffma2(v0d, x0, a);
        b = ffma2(v0d, fmul2(x0, x0), b);
        a = ffma2(v1d, x1, a);
        b = ffma2(v1d, fmul2(x1, x1), b);
    }
    if (e < end) {
        int c0 = cs[e]; float v0 = vs[e];
        u64 x0 = *(const u64*)&g_X[c0 * D + 2 * lane];
        u64 v0d = f2dup(v0);
        a = ffma2(v0d, x0, a);
        b = ffma2(v0d, fmul2(x0, x0), b);
    }
    *(u64*)&g_S3[r][gw * D + 2 * lane] = a;
    *(u64*)&g_S2_3[r][gw * D + 2 * lane] = b;
}

// -------- fused GEMM: h12 = (S+X)@linW + S2@interW + b ; att = mean tanh(h12@aW+ab)@avec --------
// 128 threads = 4 warps, each warp handles 16 rows; register-blocked, packed f32x2.
// dyn smem: wL[4096] wI[4096] wA[4096] b12[64] bA[64] aV[64] stage[4][2048]
#define GEMM_SMEM_FLOATS (3 * 4096 + 3 * 64 + 4 * 2048)

__global__ void __launch_bounds__(128) gemm3_kernel(
    int l,
    const float* __restrict__ lin_W, const float* __restrict__ lin_b,
    const float* __restrict__ inter_W, const float* __restrict__ inter_b,
    const float* __restrict__ attW0, const float* __restrict__ attW1, const float* __restrict__ attW2,
    const float* __restrict__ attb0, const float* __restrict__ attb1, const float* __restrict__ attb2,
    const float* __restrict__ av0,   const float* __restrict__ av1,   const float* __restrict__ av2)
{
    extern __shared__ float sm[];
    float* wL  = sm;
    float* wI  = sm + 4096;
    float* wA  = sm + 8192;
    float* b12 = sm + 12288;
    float* bA  = sm + 12352;
    float* aV  = sm + 12416;
    float* stage = sm + 12480;

    int r = blockIdx.y;
    const float* attW = ((r == 0) ? attW0 : (r == 1) ? attW1 : attW2) + l * 4096;
    const float* attb = ((r == 0) ? attb0 : (r == 1) ? attb1 : attb2) + l * 64;
    const float* avec = ((r == 0) ? av0   : (r == 1) ? av1   : av2)   + l * 64;

    int tid = threadIdx.x;
    for (int i = tid; i < 4096; i += 128) {
        wL[i] = lin_W[l * 4096 + i];
        wI[i] = inter_W[l * 4096 + i];
        wA[i] = attW[i];
    }
    if (tid < 64) {
        b12[tid] = lin_b[l * 64 + tid] + inter_b[l * 64 + tid];
        bA[tid] = attb[tid];
        aV[tid] = avec[tid];
    }
    __syncthreads();

    int w = tid >> 5, lane = tid & 31;
    int rowBase = blockIdx.x * 64 + w * 16;
    float* sT  = stage + w * 2048;        // [64][16]  (S+X) transposed
    float* s2T = sT + 1024;               // [64][16]  S2 transposed
    const float* __restrict__ Srel  = g_S3[r];
    const float* __restrict__ S2rel = g_S2_3[r];
    float* __restrict__ h12out = g_h12[r];

    // ---- stage 16 rows transposed ----
    #pragma unroll
    for (int mi = 0; mi < 16; mi++) {
        int m = (mi + lane) & 15;
        int row = rowBase + m;
        float2 sv, xv, s2v;
        if (row < NN) {
            sv  = *(const float2*)&Srel [row * D + 2 * lane];
            xv  = *(const float2*)&g_X  [row * D + 2 * lane];
            s2v = *(const float2*)&S2rel[row * D + 2 * lane];
        } else {
            sv = make_float2(0.f, 0.f); xv = sv; s2v = sv;
        }
        sT [(2 * lane) * 16 + m]     = sv.x + xv.x;
        sT [(2 * lane + 1) * 16 + m] = sv.y + xv.y;
        s2T[(2 * lane) * 16 + m]     = s2v.x;
        s2T[(2 * lane + 1) * 16 + m] = s2v.y;
    }
    __syncwarp();

    // ---- h12 = (S+X)@wL + S2@wI + b12 ; packed over row pairs ----
    u64 acc0[8], acc1[8];
    {
        u64 i0 = f2dup(b12[lane]), i1 = f2dup(b12[lane + 32]);
        #pragma unroll
        for (int mp = 0; mp < 8; mp++) { acc0[mp] = i0; acc1[mp] = i1; }
    }
    #pragma unroll 2
    for (int d = 0; d < 64; d++) {
        float wl0 = wL[d * 64 + lane],      wl1 = wL[d * 64 + lane + 32];
        float wi0 = wI[d * 64 + lane],      wi1 = wI[d * 64 + lane + 32];
        u64 wl0d = f2dup(wl0), wl1d = f2dup(wl1);
        u64 wi0d = f2dup(wi0), wi1d = f2dup(wi1);
        const ulonglong2* sp  = (const ulonglong2*)&sT [d * 16];
        const ulonglong2* s2p = (const ulonglong2*)&s2T[d * 16];
        u64 sd[8], s2d[8];
        #pragma unroll
        for (int q = 0; q < 4; q++) {
            ulonglong2 a = sp[q];  sd[2 * q] = a.x;  sd[2 * q + 1] = a.y;
            ulonglong2 b = s2p[q]; s2d[2 * q] = b.x; s2d[2 * q + 1] = b.y;
        }
        #pragma unroll
        for (int mp = 0; mp < 8; mp++) {
            acc0[mp] = ffma2(wl0d, sd[mp], acc0[mp]);
            acc0[mp] = ffma2(wi0d, s2d[mp], acc0[mp]);
            acc1[mp] = ffma2(wl1d, sd[mp], acc1[mp]);
            acc1[mp] = ffma2(wi1d, s2d[mp], acc1[mp]);
        }
    }

    // ---- write h12 to global ----
    #pragma unroll
    for (int mp = 0; mp < 8; mp++) {
        float lo, hi;
        int r0 = rowBase + 2 * mp, r1 = r0 + 1;
        funpack2(acc0[mp], lo, hi);
        if (r0 < NN) h12out[r0 * D + lane] = lo;
        if (r1 < NN) h12out[r1 * D + lane] = hi;
        funpack2(acc1[mp], lo, hi);
        if (r0 < NN) h12out[r0 * D + lane + 32] = lo;
        if (r1 < NN) h12out[r1 * D + lane + 32] = hi;
    }
    __syncwarp();

    // ---- stage h transposed (reuse sT region: hT[col][m]) ----
    #pragma unroll
    for (int mp = 0; mp < 8; mp++) {
        *(u64*)&sT[lane * 16 + 2 * mp] = acc0[mp];
        *(u64*)&sT[(lane + 32) * 16 + 2 * mp] = acc1[mp];
    }
    __syncwarp();

    // ---- z = h @ wA + bA ----
    u64 z0[8], z1[8];
    {
        u64 i0 = f2dup(bA[lane]), i1 = f2dup(bA[lane + 32]);
        #pragma unroll
        for (int mp = 0; mp < 8; mp++) { z0[mp] = i0; z1[mp] = i1; }
    }
    #pragma unroll 2
    for (int d = 0; d < 64; d++) {
        float wa0 = wA[d * 64 + lane], wa1 = wA[d * 64 + lane + 32];
        u64 wa0d = f2dup(wa0), wa1d = f2dup(wa1);
        const ulonglong2* hp = (const ulonglong2*)&sT[d * 16];
        u64 hd[8];
        #pragma unroll
        for (int q = 0; q < 4; q++) {
            ulonglong2 a = hp[q]; hd[2 * q] = a.x; hd[2 * q + 1] = a.y;
        }
        #pragma unroll
        for (int mp = 0; mp < 8; mp++) {
            z0[mp] = ffma2(wa0d, hd[mp], z0[mp]);
            z1[mp] = ffma2(wa1d, hd[mp], z1[mp]);
        }
    }

    // ---- attention contribution: sum over valid rows of tanh(z)@avec ----
    float aVl = aV[lane], aVh = aV[lane + 32];
    float attLocal = 0.f;
    #pragma unroll
    for (int mp = 0; mp < 8; mp++) {
        float z0l, z0h, z1l, z1h;
        funpack2(z0[mp], z0l, z0h);
        funpack2(z1[mp], z1l, z1h);
        float c0 = tanhf(z0l) * aVl + tanhf(z1l) * aVh;   // row 2mp
        float c1 = tanhf(z0h) * aVl + tanhf(z1h) * aVh;   // row 2mp+1
        if (rowBase + 2 * mp < NN)     attLocal += c0;
        if (rowBase + 2 * mp + 1 < NN) attLocal += c1;
    }
    #pragma unroll
    for (int off = 16; off; off >>= 1)
        attLocal += __shfl_down_sync(0xffffffffu, attLocal, off);
    if (lane == 0) atomicAdd(&g_attsum[r], attLocal);
}

__global__ void beta_kernel() {
    float m = g_attsum[0] / (float)NN;
    float t = g_attsum[1] / (float)NN;
    float a = g_attsum[2] / (float)NN;
    float mx = fmaxf(m, fmaxf(a, t));
    float e0 = expf(m - mx), e1 = expf(a - mx), e2 = expf(t - mx);
    float s = e0 + e1 + e2;
    g_betaRel[0] = e0 / s;
    g_betaRel[1] = e2 / s;
    g_betaRel[2] = e1 / s;
    g_attsum[0] = 0.f; g_attsum[1] = 0.f; g_attsum[2] = 0.f;
}

__global__ void combine_kernel() {
    int i = blockIdx.x * blockDim.x + threadIdx.x;
    if (i < NN * D / 4) {
        float b0 = g_betaRel[0], b1 = g_betaRel[1], b2 = g_betaRel[2];
        float4 h0 = ((const float4*)g_h12[0])[i];
        float4 h1 = ((const float4*)g_h12[1])[i];
        float4 h2 = ((const float4*)g_h12[2])[i];
        float4 v;
        v.x = b0 * h0.x + b1 * h1.x + b2 * h2.x;
        v.y = b0 * h0.y + b1 * h1.y + b2 * h2.y;
        v.z = b0 * h0.z + b1 * h1.z + b2 * h2.z;
        v.w = b0 * h0.w + b1 * h1.w + b2 * h2.w;
        ((float4*)g_X)[i] = v;
        float4 f = ((const float4*)g_facc)[i];
        f.x += v.x; f.y += v.y; f.z += v.z; f.w += v.w;
        ((float4*)g_facc)[i] = f;
    }
}

__global__ void finalize_kernel(float* __restrict__ finalOut) {
    int i = blockIdx.x * blockDim.x + threadIdx.x;
    if (i < NN * D / 4) {
        float4 f = ((const float4*)g_facc)[i];
        const float k = 1.0f / 3.0f;
        f.x *= k; f.y *= k; f.z *= k; f.w *= k;
        ((float4*)finalOut)[i] = f;
    }
}

__global__ void mlp_kernel(const int* __restrict__ userIdx, const int* __restrict__ itemIdx,
                           const float* __restrict__ W1, const float* __restrict__ b1,
                           const float* __restrict__ W2, const float* __restrict__ b2,
                           const float* __restrict__ W3, const float* __restrict__ b3,
                           const float* __restrict__ finalE,
                           float* __restrict__ pred, float* __restrict__ outU, float* __restrict__ outI)
{
    __shared__ float h[128];
    __shared__ float h1s[64];
    __shared__ float h2s[32];
    int bI = blockIdx.x;
    int t = threadIdx.x;
    int u = userIdx[bI];
    int v = itemIdx[bI] + N_USER;
    float fu = finalE[u * D + t];
    float fi = finalE[v * D + t];
    h[t] = fu; h[64 + t] = fi;
    outU[bI * D + t] = fu;
    outI[bI * D + t] = fi;
    __syncthreads();

    float acc = b1[t];
    #pragma unroll 16
    for (int k = 0; k < 128; k++) acc += h[k] * W1[k * 64 + t];
    h1s[t] = fmaxf(acc, 0.f);
    __syncthreads();

    if (t < 32) {
        float a2 = b2[t];
        #pragma unroll 16
        for (int k = 0; k < 64; k++) a2 += h1s[k] * W2[k * 32 + t];
        h2s[t] = a2;
    }
    __syncthreads();
    if (t < 32) {
        float p = h2s[t] * W3[t];
        #pragma unroll
        for (int off = 16; off; off >>= 1) p += __shfl_down_sync(0xffffffffu, p, off);
        if (t == 0) pred[bI] = p + b3[0];
    }
}

// ---------------- launch ----------------
extern "C" void kernel_launch(void* const* d_in, const int* in_sizes, int n_in,
                              void* d_out, int out_size)
{
    const int*   userIdx = (const int*)d_in[0];
    const int*   itemIdx = (const int*)d_in[1];
    const float* uEmbd   = (const float*)d_in[2];
    const float* iEmbd   = (const float*)d_in[3];

    const int*   rowP[3] = { (const int*)d_in[4],  (const int*)d_in[7],  (const int*)d_in[10] };
    const int*   colP[3] = { (const int*)d_in[5],  (const int*)d_in[8],  (const int*)d_in[11] };
    const float* valP[3] = { (const float*)d_in[6], (const float*)d_in[9], (const float*)d_in[12] };

    const float *lin_W, *lin_b, *inter_W, *inter_b;
    const float *attM_W, *attM_b, *attA_W, *attA_b, *attT_W, *attT_b;
    if (in_sizes[14] == 2 * D * D) {
        lin_W   = (const float*)d_in[13];
        inter_W = (const float*)d_in[14];
        attM_W  = (const float*)d_in[15];
        attA_W  = (const float*)d_in[16];
        attT_W  = (const float*)d_in[17];
        lin_b   = (const float*)d_in[18];
        inter_b = (const float*)d_in[19];
        attM_b  = (const float*)d_in[20];
        attA_b  = (const float*)d_in[21];
        attT_b  = (const float*)d_in[22];
    } else {
        lin_W   = (const float*)d_in[13];
        lin_b   = (const float*)d_in[14];
        inter_W = (const float*)d_in[15];
        inter_b = (const float*)d_in[16];
        attM_W  = (const float*)d_in[17];
        attM_b  = (const float*)d_in[18];
        attA_W  = (const float*)d_in[19];
        attA_b  = (const float*)d_in[20];
        attT_W  = (const float*)d_in[21];
        attT_b  = (const float*)d_in[22];
    }
    const float* a_main  = (const float*)d_in[23];
    const float* a_add   = (const float*)d_in[24];
    const float* a_trust = (const float*)d_in[25];
    const float* W1 = (const float*)d_in[26];
    const float* b1 = (const float*)d_in[27];
    const float* W2 = (const float*)d_in[28];
    const float* b2 = (const float*)d_in[29];
    const float* W3 = (const float*)d_in[30];
    const float* b3 = (const float*)d_in[31];

    float* out      = (float*)d_out;
    float* predOut  = out;
    float* userOut  = out + BB;
    float* itemOut  = out + BB + BB * D;
    float* finalOut = out + BB + 2 * BB * D;

    const int TPB = 256;
    const int ND4_BLOCKS = (NN * D / 4 + TPB - 1) / TPB;
    const int GEMM_SMEM_BYTES = GEMM_SMEM_FLOATS * 4;

    cudaFuncSetAttribute(gemm3_kernel, cudaFuncAttributeMaxDynamicSharedMemorySize,
                         GEMM_SMEM_BYTES);

    zero3_kernel<<<(3 * NN + TPB - 1) / TPB, TPB>>>();
    init_feats_kernel<<<ND4_BLOCKS, TPB>>>(uEmbd, iEmbd);

    dim3 edgeGrid((NNZ + TPB - 1) / TPB, 3);
    hist3_kernel<<<edgeGrid, TPB>>>(rowP[0], rowP[1], rowP[2]);
    scan_local_kernel<<<dim3(NB, 3), 1024>>>();
    scan_blk_kernel<<<1, 384>>>();
    fixup_kernel<<<dim3(NB, 3), 1024>>>();
    scatter3_kernel<<<edgeGrid, TPB>>>(rowP[0], rowP[1], rowP[2],
                                       colP[0], colP[1], colP[2],
                                       valP[0], valP[1], valP[2]);

    dim3 spmmGrid((NN * 32 + TPB - 1) / TPB, 3);
    dim3 gemmGrid((NN + 63) / 64, 3);
    for (int l = 0; l < NLAYERS; l++) {
        spmm3_kernel<<<spmmGrid, TPB>>>();
        gemm3_kernel<<<gemmGrid, 128, GEMM_SMEM_BYTES>>>(
            l, lin_W, lin_b, inter_W, inter_b,
            attM_W, attT_W, attA_W,
            attM_b, attT_b, attA_b,
            a_main, a_trust, a_add);
        beta_kernel<<<1, 1>>>();
        combine_kernel<<<ND4_BLOCKS, TPB>>>();
    }

    finalize_kernel<<<ND4_BLOCKS, TPB>>>(finalOut);
    mlp_kernel<<<BB, 64>>>(userIdx, itemIdx, W1, b1, W2, b2, W3, b3,
                           finalOut, predOut, userOut, itemOut);
}

// round 4
// speedup vs baseline: 2.3583x; 1.2109x over previous
#include <cuda_runtime.h>
#include <cuda_bf16.h>
#include <math.h>
#include <stdint.h>

#define N_USER 60000
#define N_ITEM 40000
#define NN     100000
#define D      64
#define NNZ    1600000
#define BB     16384
#define NLAYERS 2
#define NB     98          // ceil(NN/1024)

typedef unsigned long long u64;

// ---------------- packed f32x2 helpers (spmm) ----------------
__device__ __forceinline__ u64 f2dup(float v) {
    u64 r; asm("mov.b64 %0,{%1,%1};" : "=l"(r) : "f"(v)); return r;
}
__device__ __forceinline__ u64 ffma2(u64 a, u64 b, u64 c) {
    u64 d; asm("fma.rn.f32x2 %0,%1,%2,%3;" : "=l"(d) : "l"(a), "l"(b), "l"(c)); return d;
}
__device__ __forceinline__ u64 fmul2(u64 a, u64 b) {
    u64 d; asm("mul.rn.f32x2 %0,%1,%2;" : "=l"(d) : "l"(a), "l"(b)); return d;
}

// ---------------- mma.sync helpers (sm_80+ ISA, legal on target sm_103) ----------------
__device__ __forceinline__ uint32_t smem_to_u32(const void* p) {
    uint32_t a;
    asm("{ .reg .u64 t; cvta.to.shared.u64 t, %1; cvt.u32.u64 %0, t; }" : "=r"(a) : "l"(p));
    return a;
}
__device__ __forceinline__ void ldsm4(uint32_t* r, uint32_t addr) {
    asm volatile("ldmatrix.sync.aligned.m8n8.x4.shared.b16 {%0,%1,%2,%3}, [%4];"
        : "=r"(r[0]), "=r"(r[1]), "=r"(r[2]), "=r"(r[3]) : "r"(addr));
}
__device__ __forceinline__ uint32_t lds32(uint32_t addr) {
    uint32_t v; asm volatile("ld.shared.b32 %0, [%1];" : "=r"(v) : "r"(addr)); return v;
}
__device__ __forceinline__ void mma16816(float* d, const uint32_t* a, const uint32_t* b) {
    asm volatile(
        "mma.sync.aligned.m16n8k16.row.col.f32.bf16.bf16.f32 "
        "{%0,%1,%2,%3}, {%4,%5,%6,%7}, {%8,%9}, {%0,%1,%2,%3};"
        : "+f"(d[0]), "+f"(d[1]), "+f"(d[2]), "+f"(d[3])
        : "r"(a[0]), "r"(a[1]), "r"(a[2]), "r"(a[3]), "r"(b[0]), "r"(b[1]));
}

__device__ __forceinline__ void split2(float a, float b, uint32_t& hi, uint32_t& lo) {
    __nv_bfloat16 ah = __float2bfloat16(a);
    __nv_bfloat16 bh = __float2bfloat16(b);
    __nv_bfloat16 al = __float2bfloat16(a - __bfloat162float(ah));
    __nv_bfloat16 bl = __float2bfloat16(b - __bfloat162float(bh));
    hi = (uint32_t)__bfloat16_as_ushort(ah) | ((uint32_t)__bfloat16_as_ushort(bh) << 16);
    lo = (uint32_t)__bfloat16_as_ushort(al) | ((uint32_t)__bfloat16_as_ushort(bl) << 16);
}

// ---------------- scratch ----------------
__device__ float g_X[NN * D];
__device__ float g_facc[NN * D];
__device__ float g_S3[3][NN * D];
__device__ float g_S2_3[3][NN * D];
__device__ float g_h12[3][NN * D];
__device__ int   g_rowptr[3][NN + 1];
__device__ u64   g_edge[3][NNZ];
__device__ int   g_count3[3][NN];
__device__ int   g_cursor3[3][NN];
__device__ int   g_blk[3][128];
__device__ float g_attsum[3];
__device__ float g_betaRel[3];

// ---------------- small kernels ----------------
__global__ void zero3_kernel() {
    int i = blockIdx.x * blockDim.x + threadIdx.x;
    if (i < 3 * NN) ((int*)g_count3)[i] = 0;
    if (i < 3) g_attsum[i] = 0.f;
}

__global__ void init_feats_kernel(const float* __restrict__ uE, const float* __restrict__ iE) {
    int i4 = blockIdx.x * blockDim.x + threadIdx.x;
    if (i4 < NN * D / 4) {
        int i = i4 * 4;
        float4 v = (i < N_USER * D) ? ((const float4*)uE)[i4]
                                    : ((const float4*)iE)[i4 - N_USER * D / 4];
        ((float4*)g_X)[i4] = v;
        ((float4*)g_facc)[i4] = v;
    }
}

__global__ void hist3_kernel(const int* __restrict__ r0, const int* __restrict__ r1,
                             const int* __restrict__ r2) {
    int r = blockIdx.y;
    const int* row = (r == 0) ? r0 : (r == 1) ? r1 : r2;
    int e = blockIdx.x * blockDim.x + threadIdx.x;
    if (e < NNZ) atomicAdd(&g_count3[r][row[e]], 1);
}

__global__ void scan_local_kernel() {
    __shared__ int s[1024];
    int r = blockIdx.y;
    int i = blockIdx.x * 1024 + threadIdx.x;
    int c = (i < NN) ? g_count3[r][i] : 0;
    s[threadIdx.x] = c;
    __syncthreads();
    for (int off = 1; off < 1024; off <<= 1) {
        int t = (threadIdx.x >= off) ? s[threadIdx.x - off] : 0;
        __syncthreads();
        s[threadIdx.x] += t;
        __syncthreads();
    }
    if (i < NN) g_rowptr[r][i] = s[threadIdx.x] - c;
    if (threadIdx.x == 1023) g_blk[r][blockIdx.x] = s[1023];
}

__global__ void scan_blk_kernel() {
    __shared__ int s[3 * NB];
    int tid = threadIdx.x;
    for (int i = tid; i < 3 * NB; i += blockDim.x) s[i] = g_blk[i / NB][i % NB];
    __syncthreads();
    if (tid < 3) {
        int run = 0;
        for (int b = 0; b < NB; b++) { int t = s[tid * NB + b]; s[tid * NB + b] = run; run += t; }
        g_rowptr[tid][NN] = run;
    }
    __syncthreads();
    for (int i = tid; i < 3 * NB; i += blockDim.x) g_blk[i / NB][i % NB] = s[i];
}

__global__ void fixup_kernel() {
    int r = blockIdx.y;
    int i = blockIdx.x * 1024 + threadIdx.x;
    if (i < NN) {
        int v = g_rowptr[r][i] + g_blk[r][blockIdx.x];
        g_rowptr[r][i] = v;
        g_cursor3[r][i] = v;
    }
}

__global__ void scatter3_kernel(const int* __restrict__ r0, const int* __restrict__ r1,
                                const int* __restrict__ r2,
                                const int* __restrict__ c0, const int* __restrict__ c1,
                                const int* __restrict__ c2,
                                const float* __restrict__ v0, const float* __restrict__ v1,
                                const float* __restrict__ v2) {
    int r = blockIdx.y;
    const int* row = (r == 0) ? r0 : (r == 1) ? r1 : r2;
    const int* col = (r == 0) ? c0 : (r == 1) ? c1 : c2;
    const float* val = (r == 0) ? v0 : (r == 1) ? v1 : v2;
    int e = blockIdx.x * blockDim.x + threadIdx.x;
    if (e < NNZ) {
        int rr = row[e];
        int pos = atomicAdd(&g_cursor3[r][rr], 1);
        u64 pk = ((u64)(uint32_t)__float_as_int(val[e]) << 32) | (uint32_t)col[e];
        g_edge[r][pos] = pk;
    }
}

// fused SpMM: S = A@X, S2 = A@(X*X); warp per row, packed f32x2, packed edges
__global__ void spmm3_kernel() {
    int r = blockIdx.y;
    int gw = (blockIdx.x * blockDim.x + threadIdx.x) >> 5;
    int lane = threadIdx.x & 31;
    if (gw >= NN) return;
    const u64* __restrict__ ed = g_edge[r];
    int beg = g_rowptr[r][gw], end = g_rowptr[r][gw + 1];
    u64 a = 0ull, b = 0ull;
    int e = beg;
    for (; e + 2 <= end; e += 2) {
        u64 p0 = ed[e], p1 = ed[e + 1];
        int   c0 = (int)(uint32_t)p0,  c1 = (int)(uint32_t)p1;
        float v0 = __uint_as_float((uint32_t)(p0 >> 32));
        float v1 = __uint_as_float((uint32_t)(p1 >> 32));
        u64 x0 = *(const u64*)&g_X[c0 * D + 2 * lane];
        u64 x1 = *(const u64*)&g_X[c1 * D + 2 * lane];
        u64 v0d = f2dup(v0), v1d = f2dup(v1);
        a = ffma2(v0d, x0, a);
        b = ffma2(v0d, fmul2(x0, x0), b);
        a = ffma2(v1d, x1, a);
        b = ffma2(v1d, fmul2(x1, x1), b);
    }
    if (e < end) {
        u64 p0 = ed[e];
        int c0 = (int)(uint32_t)p0;
        float v0 = __uint_as_float((uint32_t)(p0 >> 32));
        u64 x0 = *(const u64*)&g_X[c0 * D + 2 * lane];
        u64 v0d = f2dup(v0);
        a = ffma2(v0d, x0, a);
        b = ffma2(v0d, fmul2(x0, x0), b);
    }
    *(u64*)&g_S3[r][gw * D + 2 * lane] = a;
    *(u64*)&g_S2_3[r][gw * D + 2 * lane] = b;
}

// ---------------- HMMA GEMM (mma.sync m16n8k16 bf16, hi/lo split) ----------------
// Per 128-row tile: h12 = (S+X)@linW + S2@interW + b, att += sum tanh(h12@attW+ab)@avec.
// smem byte offsets (ushort arrays, row stride 72 elems = 144 B, 16B aligned)
#define STRD 72
#define OFF_AH   0
#define OFF_AL   18432
#define OFF_A2H  36864
#define OFF_A2L  55296
#define OFF_WLH  73728
#define OFF_WLL  82944
#define OFF_WIH  92160
#define OFF_WIL  101376
#define OFF_WAH  110592
#define OFF_WAL  119808
#define OFF_B12  129024
#define OFF_BA   129280
#define OFF_AV   129536
#define GEMM_SMEM_BYTES 130048

__global__ void __launch_bounds__(256) gemm_mma_kernel(
    int l,
    const float* __restrict__ lin_W, const float* __restrict__ lin_b,
    const float* __restrict__ inter_W, const float* __restrict__ inter_b,
    const float* __restrict__ attW0, const float* __restrict__ attW1, const float* __restrict__ attW2,
    const float* __restrict__ attb0, const float* __restrict__ attb1, const float* __restrict__ attb2,
    const float* __restrict__ av0,   const float* __restrict__ av1,   const float* __restrict__ av2)
{
    extern __shared__ char smc[];
    uint32_t sbase = smem_to_u32(smc);

    int r = blockIdx.y;
    const float* attW = ((r == 0) ? attW0 : (r == 1) ? attW1 : attW2) + l * 4096;
    const float* attb = ((r == 0) ? attb0 : (r == 1) ? attb1 : attb2) + l * 64;
    const float* avec = ((r == 0) ? av0   : (r == 1) ? av1   : av2)   + l * 64;

    int t = threadIdx.x, wid = t >> 5, lane = t & 31;
    int warpRow = wid * 16;
    int rowBase = blockIdx.x * 128;

    // ---- stage weights transposed [n][k], bf16 hi/lo ----
    for (int i = t; i < 4096; i += 256) {
        int k = i >> 6, n = i & 63;
        uint32_t so = (uint32_t)(n * STRD + k) * 2;
        float wl = lin_W[l * 4096 + i];
        float wi = inter_W[l * 4096 + i];
        float wa = attW[i];
        __nv_bfloat16 h;
        h = __float2bfloat16(wl);
        *(unsigned short*)(smc + OFF_WLH + so) = __bfloat16_as_ushort(h);
        *(unsigned short*)(smc + OFF_WLL + so) = __bfloat16_as_ushort(__float2bfloat16(wl - __bfloat162float(h)));
        h = __float2bfloat16(wi);
        *(unsigned short*)(smc + OFF_WIH + so) = __bfloat16_as_ushort(h);
        *(unsigned short*)(smc + OFF_WIL + so) = __bfloat16_as_ushort(__float2bfloat16(wi - __bfloat162float(h)));
        h = __float2bfloat16(wa);
        *(unsigned short*)(smc + OFF_WAH + so) = __bfloat16_as_ushort(h);
        *(unsigned short*)(smc + OFF_WAL + so) = __bfloat16_as_ushort(__float2bfloat16(wa - __bfloat162float(h)));
    }
    if (t < 64) {
        ((float*)(smc + OFF_B12))[t] = lin_b[l * 64 + t] + inter_b[l * 64 + t];
        ((float*)(smc + OFF_BA))[t]  = attb[t];
        ((float*)(smc + OFF_AV))[t]  = avec[t];
    }

    // ---- stage A rows: (S+X) and S2, bf16 hi/lo split ----
    {
        int lr = t >> 1;
        int c0 = (t & 1) * 32;
        int grow = rowBase + lr;
        bool v = grow < NN;
        const float4* S4  = (const float4*)(g_S3[r]   + (size_t)(v ? grow : 0) * 64 + c0);
        const float4* X4  = (const float4*)(g_X       + (size_t)(v ? grow : 0) * 64 + c0);
        const float4* S24 = (const float4*)(g_S2_3[r] + (size_t)(v ? grow : 0) * 64 + c0);
        #pragma unroll
        for (int j = 0; j < 8; j++) {
            float4 sv = S4[j], xv = X4[j], s2v = S24[j];
            float a0 = sv.x + xv.x, a1 = sv.y + xv.y, a2 = sv.z + xv.z, a3 = sv.w + xv.w;
            float b0 = s2v.x, b1 = s2v.y, b2 = s2v.z, b3 = s2v.w;
            if (!v) { a0=a1=a2=a3=0.f; b0=b1=b2=b3=0.f; }
            uint32_t hi, lo;
            uint32_t base = (uint32_t)(lr * STRD + c0 + 4 * j) * 2;
            split2(a0, a1, hi, lo);
            *(uint32_t*)(smc + OFF_AH + base) = hi;
            *(uint32_t*)(smc + OFF_AL + base) = lo;
            split2(a2, a3, hi, lo);
            *(uint32_t*)(smc + OFF_AH + base + 4) = hi;
            *(uint32_t*)(smc + OFF_AL + base + 4) = lo;
            split2(b0, b1, hi, lo);
            *(uint32_t*)(smc + OFF_A2H + base) = hi;
            *(uint32_t*)(smc + OFF_A2L + base) = lo;
            split2(b2, b3, hi, lo);
            *(uint32_t*)(smc + OFF_A2H + base + 4) = hi;
            *(uint32_t*)(smc + OFF_A2L + base + 4) = lo;
        }
    }
    __syncthreads();

    // ---- phase 1: h12 = Ah(WLh+WLl)+Al WLh + A2h(WIh+WIl)+A2l WIh ----
    float acc[8][4];
    #pragma unroll
    for (int n = 0; n < 8; n++)
        #pragma unroll
        for (int q = 0; q < 4; q++) acc[n][q] = 0.f;

    int lr = lane & 15, kh = lane >> 4;
    int gid = lane >> 2, qk = lane & 3;

    #pragma unroll
    for (int kt = 0; kt < 4; kt++) {
        uint32_t rowoff = (uint32_t)((warpRow + lr) * STRD + kt * 16 + kh * 8) * 2;
        uint32_t aH[4], aL[4], a2H[4], a2L[4];
        ldsm4(aH,  sbase + OFF_AH  + rowoff);
        ldsm4(aL,  sbase + OFF_AL  + rowoff);
        ldsm4(a2H, sbase + OFF_A2H + rowoff);
        ldsm4(a2L, sbase + OFF_A2L + rowoff);
        #pragma unroll
        for (int nt = 0; nt < 8; nt++) {
            uint32_t wb = (uint32_t)((nt * 8 + gid) * STRD + kt * 16 + qk * 2) * 2;
            uint32_t bWLh[2], bWLl[2], bWIh[2], bWIl[2];
            bWLh[0] = lds32(sbase + OFF_WLH + wb); bWLh[1] = lds32(sbase + OFF_WLH + wb + 16);
            bWLl[0] = lds32(sbase + OFF_WLL + wb); bWLl[1] = lds32(sbase + OFF_WLL + wb + 16);
            bWIh[0] = lds32(sbase + OFF_WIH + wb); bWIh[1] = lds32(sbase + OFF_WIH + wb + 16);
            bWIl[0] = lds32(sbase + OFF_WIL + wb); bWIl[1] = lds32(sbase + OFF_WIL + wb + 16);
            mma16816(acc[nt], aH, bWLh);
            mma16816(acc[nt], aH, bWLl);
            mma16816(acc[nt], aL, bWLh);
            mma16816(acc[nt], a2H, bWIh);
            mma16816(acc[nt], a2H, bWIl);
            mma16816(acc[nt], a2L, bWIh);
        }
    }
    __syncwarp();

    // ---- write h12 (global) + stage h hi/lo into AH/AL (reuse) ----
    const float* b12 = (const float*)(smc + OFF_B12);
    float* __restrict__ h12out = g_h12[r];
    int row0 = rowBase + warpRow + gid;
    int row1 = row0 + 8;
    #pragma unroll
    for (int nt = 0; nt < 8; nt++) {
        int col = nt * 8 + qk * 2;
        float h00 = acc[nt][0] + b12[col], h01 = acc[nt][1] + b12[col + 1];
        float h10 = acc[nt][2] + b12[col], h11 = acc[nt][3] + b12[col + 1];
        if (row0 < NN) *(float2*)&h12out[(size_t)row0 * 64 + col] = make_float2(h00, h01);
        if (row1 < NN) *(float2*)&h12out[(size_t)row1 * 64 + col] = make_float2(h10, h11);
        uint32_t hi, lo;
        uint32_t so0 = (uint32_t)((warpRow + gid) * STRD + col) * 2;
        uint32_t so1 = (uint32_t)((warpRow + gid + 8) * STRD + col) * 2;
        split2(h00, h01, hi, lo);
        *(uint32_t*)(smc + OFF_AH + so0) = hi;
        *(uint32_t*)(smc + OFF_AL + so0) = lo;
        split2(h10, h11, hi, lo);
        *(uint32_t*)(smc + OFF_AH + so1) = hi;
        *(uint32_t*)(smc + OFF_AL + so1) = lo;
    }
    __syncwarp();

    // ---- phase 2: z = Hh(WAh+WAl) + Hl WAh ----
    float zac[8][4];
    #pragma unroll
    for (int n = 0; n < 8; n++)
        #pragma unroll
        for (int q = 0; q < 4; q++) zac[n][q] = 0.f;

    #pragma unroll
    for (int kt = 0; kt < 4; kt++) {
        uint32_t rowoff = (uint32_t)((warpRow + lr) * STRD + kt * 16 + kh * 8) * 2;
        uint32_t hH[4], hL[4];
        ldsm4(hH, sbase + OFF_AH + rowoff);
        ldsm4(hL, sbase + OFF_AL + rowoff);
        #pragma unroll
        for (int nt = 0; nt < 8; nt++) {
            uint32_t wb = (uint32_t)((nt * 8 + gid) * STRD + kt * 16 + qk * 2) * 2;
            uint32_t bWAh[2], bWAl[2];
            bWAh[0] = lds32(sbase + OFF_WAH + wb); bWAh[1] = lds32(sbase + OFF_WAH + wb + 16);
            bWAl[0] = lds32(sbase + OFF_WAL + wb); bWAl[1] = lds32(sbase + OFF_WAL + wb + 16);
            mma16816(zac[nt], hH, bWAh);
            mma16816(zac[nt], hH, bWAl);
            mma16816(zac[nt], hL, bWAh);
        }
    }

    // ---- att: sum tanh(z+bA)*aV ----
    const float* bA = (const float*)(smc + OFF_BA);
    const float* aV = (const float*)(smc + OFF_AV);
    float attLocal = 0.f;
    bool v0 = row0 < NN, v1 = row1 < NN;
    #pragma unroll
    for (int nt = 0; nt < 8; nt++) {
        int col = nt * 8 + qk * 2;
        float av0c = aV[col], av1c = aV[col + 1];
        float bc0 = bA[col], bc1 = bA[col + 1];
        if (v0) attLocal += tanhf(zac[nt][0] + bc0) * av0c + tanhf(zac[nt][1] + bc1) * av1c;
        if (v1) attLocal += tanhf(zac[nt][2] + bc0) * av0c + tanhf(zac[nt][3] + bc1) * av1c;
    }
    #pragma unroll
    for (int off = 16; off; off >>= 1)
        attLocal += __shfl_down_sync(0xffffffffu, attLocal, off);
    if (lane == 0) atomicAdd(&g_attsum[r], attLocal);
}

// ---------------- tail kernels ----------------
__global__ void beta_kernel() {
    float m = g_attsum[0] / (float)NN;
    float t = g_attsum[1] / (float)NN;
    float a = g_attsum[2] / (float)NN;
    float mx = fmaxf(m, fmaxf(a, t));
    float e0 = expf(m - mx), e1 = expf(a - mx), e2 = expf(t - mx);
    float s = e0 + e1 + e2;
    g_betaRel[0] = e0 / s;
    g_betaRel[1] = e2 / s;
    g_betaRel[2] = e1 / s;
    g_attsum[0] = 0.f; g_attsum[1] = 0.f; g_attsum[2] = 0.f;
}

__global__ void combine_kernel() {
    int i = blockIdx.x * blockDim.x + threadIdx.x;
    if (i < NN * D / 4) {
        float b0 = g_betaRel[0], b1 = g_betaRel[1], b2 = g_betaRel[2];
        float4 h0 = ((const float4*)g_h12[0])[i];
        float4 h1 = ((const float4*)g_h12[1])[i];
        float4 h2 = ((const float4*)g_h12[2])[i];
        float4 v;
        v.x = b0 * h0.x + b1 * h1.x + b2 * h2.x;
        v.y = b0 * h0.y + b1 * h1.y + b2 * h2.y;
        v.z = b0 * h0.z + b1 * h1.z + b2 * h2.z;
        v.w = b0 * h0.w + b1 * h1.w + b2 * h2.w;
        ((float4*)g_X)[i] = v;
        float4 f = ((const float4*)g_facc)[i];
        f.x += v.x; f.y += v.y; f.z += v.z; f.w += v.w;
        ((float4*)g_facc)[i] = f;
    }
}

__global__ void finalize_kernel(float* __restrict__ finalOut) {
    int i = blockIdx.x * blockDim.x + threadIdx.x;
    if (i < NN * D / 4) {
        float4 f = ((const float4*)g_facc)[i];
        const float k = 1.0f / 3.0f;
        f.x *= k; f.y *= k; f.z *= k; f.w *= k;
        ((float4*)finalOut)[i] = f;
    }
}

__global__ void mlp_kernel(const int* __restrict__ userIdx, const int* __restrict__ itemIdx,
                           const float* __restrict__ W1, const float* __restrict__ b1,
                           const float* __restrict__ W2, const float* __restrict__ b2,
                           const float* __restrict__ W3, const float* __restrict__ b3,
                           const float* __restrict__ finalE,
                           float* __restrict__ pred, float* __restrict__ outU, float* __restrict__ outI)
{
    __shared__ float h[128];
    __shared__ float h1s[64];
    __shared__ float h2s[32];
    int bI = blockIdx.x;
    int t = threadIdx.x;
    int u = userIdx[bI];
    int v = itemIdx[bI] + N_USER;
    float fu = finalE[u * D + t];
    float fi = finalE[v * D + t];
    h[t] = fu; h[64 + t] = fi;
    outU[bI * D + t] = fu;
    outI[bI * D + t] = fi;
    __syncthreads();

    float acc = b1[t];
    #pragma unroll 16
    for (int k = 0; k < 128; k++) acc += h[k] * W1[k * 64 + t];
    h1s[t] = fmaxf(acc, 0.f);
    __syncthreads();

    if (t < 32) {
        float a2 = b2[t];
        #pragma unroll 16
        for (int k = 0; k < 64; k++) a2 += h1s[k] * W2[k * 32 + t];
        h2s[t] = a2;
    }
    __syncthreads();
    if (t < 32) {
        float p = h2s[t] * W3[t];
        #pragma unroll
        for (int off = 16; off; off >>= 1) p += __shfl_down_sync(0xffffffffu, p, off);
        if (t == 0) pred[bI] = p + b3[0];
    }
}

// ---------------- launch ----------------
extern "C" void kernel_launch(void* const* d_in, const int* in_sizes, int n_in,
                              void* d_out, int out_size)
{
    const int*   userIdx = (const int*)d_in[0];
    const int*   itemIdx = (const int*)d_in[1];
    const float* uEmbd   = (const float*)d_in[2];
    const float* iEmbd   = (const float*)d_in[3];

    const int*   rowP[3] = { (const int*)d_in[4],  (const int*)d_in[7],  (const int*)d_in[10] };
    const int*   colP[3] = { (const int*)d_in[5],  (const int*)d_in[8],  (const int*)d_in[11] };
    const float* valP[3] = { (const float*)d_in[6], (const float*)d_in[9], (const float*)d_in[12] };

    const float *lin_W, *lin_b, *inter_W, *inter_b;
    const float *attM_W, *attM_b, *attA_W, *attA_b, *attT_W, *attT_b;
    if (in_sizes[14] == 2 * D * D) {
        lin_W   = (const float*)d_in[13];
        inter_W = (const float*)d_in[14];
        attM_W  = (const float*)d_in[15];
        attA_W  = (const float*)d_in[16];
        attT_W  = (const float*)d_in[17];
        lin_b   = (const float*)d_in[18];
        inter_b = (const float*)d_in[19];
        attM_b  = (const float*)d_in[20];
        attA_b  = (const float*)d_in[21];
        attT_b  = (const float*)d_in[22];
    } else {
        lin_W   = (const float*)d_in[13];
        lin_b   = (const float*)d_in[14];
        inter_W = (const float*)d_in[15];
        inter_b = (const float*)d_in[16];
        attM_W  = (const float*)d_in[17];
        attM_b  = (const float*)d_in[18];
        attA_W  = (const float*)d_in[19];
        attA_b  = (const float*)d_in[20];
        attT_W  = (const float*)d_in[21];
        attT_b  = (const float*)d_in[22];
    }
    const float* a_main  = (const float*)d_in[23];
    const float* a_add   = (const float*)d_in[24];
    const float* a_trust = (const float*)d_in[25];
    const float* W1 = (const float*)d_in[26];
    const float* b1 = (const float*)d_in[27];
    const float* W2 = (const float*)d_in[28];
    const float* b2 = (const float*)d_in[29];
    const float* W3 = (const float*)d_in[30];
    const float* b3 = (const float*)d_in[31];

    float* out      = (float*)d_out;
    float* predOut  = out;
    float* userOut  = out + BB;
    float* itemOut  = out + BB + BB * D;
    float* finalOut = out + BB + 2 * BB * D;

    const int TPB = 256;
    const int ND4_BLOCKS = (NN * D / 4 + TPB - 1) / TPB;

    cudaFuncSetAttribute(gemm_mma_kernel, cudaFuncAttributeMaxDynamicSharedMemorySize,
                         GEMM_SMEM_BYTES);

    zero3_kernel<<<(3 * NN + TPB - 1) / TPB, TPB>>>();
    init_feats_kernel<<<ND4_BLOCKS, TPB>>>(uEmbd, iEmbd);

    dim3 edgeGrid((NNZ + TPB - 1) / TPB, 3);
    hist3_kernel<<<edgeGrid, TPB>>>(rowP[0], rowP[1], rowP[2]);
    scan_local_kernel<<<dim3(NB, 3), 1024>>>();
    scan_blk_kernel<<<1, 384>>>();
    fixup_kernel<<<dim3(NB, 3), 1024>>>();
    scatter3_kernel<<<edgeGrid, TPB>>>(rowP[0], rowP[1], rowP[2],
                                       colP[0], colP[1], colP[2],
                                       valP[0], valP[1], valP[2]);

    dim3 spmmGrid((NN * 32 + TPB - 1) / TPB, 3);
    dim3 gemmGrid((NN + 127) / 128, 3);
    for (int l = 0; l < NLAYERS; l++) {
        spmm3_kernel<<<spmmGrid, TPB>>>();
        gemm_mma_kernel<<<gemmGrid, 256, GEMM_SMEM_BYTES>>>(
            l, lin_W, lin_b, inter_W, inter_b,
            attM_W, attT_W, attA_W,
            attM_b, attT_b, attA_b,
            a_main, a_trust, a_add);
        beta_kernel<<<1, 1>>>();
        combine_kernel<<<ND4_BLOCKS, TPB>>>();
    }

    finalize_kernel<<<ND4_BLOCKS, TPB>>>(finalOut);
    mlp_kernel<<<BB, 64>>>(userIdx, itemIdx, W1, b1, W2, b2, W3, b3,
                           finalOut, predOut, userOut, itemOut);
}